// round 11
// baseline (speedup 1.0000x reference)
#include <cuda_runtime.h>

// Grouped shifted conv1d:
//   t = roll(x, +1, axis=3); patches = unfold(t, k=3, pad=1) along last axis
//   y[o,k,n,m] = sum_{i,j} patches[o*64+i, n, j, m] * W[i,k,j]
//   out = roll(y, +1, axis=2)  (H roll folded into store index)
//
// Grid: (56 rows, 2 groups, 2 k-halves) = 224 CTAs -> ~2 independent CTAs/SM,
// overlapping each other's DRAM prologue and barrier/reduction tails.
// Block: 448 = 14 mq x 2 kq x 16 iq. Thread: 4m x 4k tile over 4 channels.
// Single-stage reduction: 16 slabs of (8 k_local x 56 m) partials.

#define NT 448
#define XPITCH 60   // floats; i*60 is 16B-aligned so float4 row loads work

union Smem {
    struct {
        float xs[64 * XPITCH];   // xs[i][u]: rolled + zero-padded, u in [0,58)
        float ws[3 * 64 * 8];    // ws[j][i][kl]: k_local contiguous (this CTA's 8 k)
    } s;
    float red[16 * 8 * 56];      // partials red[iq][k_local][m], aliases after compute
};

__global__ void __launch_bounds__(NT)
shiftconv_kernel(const float* __restrict__ x,
                 const float* __restrict__ W,
                 float* __restrict__ out)
{
    __shared__ Smem sm;

    const int n  = blockIdx.x;   // input H row 0..55
    const int o  = blockIdx.y;   // channel group 0..1
    const int kh = blockIdx.z;   // k half 0..1 (global k = kh*8 + k_local)

    const int tid = threadIdx.x;
    const int mq  = tid % 14;          // 4-wide m tile index
    const int kq  = (tid / 14) % 2;    // 4-wide k_local tile index (0..1)
    const int iq  = tid / 28;          // 0..15, 4-channel slice

    // zero pad columns u=0 and u=57
    if (tid < 128)
        sm.s.xs[(tid >> 1) * XPITCH + (tid & 1) * 57] = 0.0f;

    // --- stage x: 8 LDGs in flight per thread (448*8 = 64*56), fused roll ---
    // 448 = 8*56: u constant per thread, i steps by 8 -> coalesced over m.
    {
        const float* xg  = x + (o * 64) * 3136 + n * 56;
        const int    u   = tid % 56 + 1;          // 1..56
        const int    src = (tid % 56 + 55) % 56;  // (u-2) mod 56
        const int    i0  = tid / 56;              // 0..7
        #pragma unroll
        for (int s = 0; s < 8; ++s) {
            const int i = i0 + 8 * s;
            sm.s.xs[i * XPITCH + u] = xg[i * 3136 + src];
        }
    }

    // --- stage W (this CTA's 8 k): src (i,k,j) -> ws[j*512 + i*8 + kl] ---
    #pragma unroll
    for (int s = 0; s < 4; ++s) {
        const int t = tid + s * NT;
        if (t < 1536) {
            const int kl = t & 7;
            const int i  = (t >> 3) & 63;
            const int j  = t >> 9;
            sm.s.ws[t] = W[i * 48 + (kh * 8 + kl) * 3 + j];
        }
    }
    __syncthreads();

    // --- compute: 4m x 4k_local register tile, i in [iq*4, iq*4+4) ---
    const int mbase = mq * 4;
    const int kbase = kq * 4;
    float acc[4][4];                       // [kk][d]
    #pragma unroll
    for (int a = 0; a < 4; ++a)
        #pragma unroll
        for (int b = 0; b < 4; ++b) acc[a][b] = 0.f;

    const float* xrow = sm.s.xs + iq * 4 * XPITCH + mbase;
    const float* wrow = sm.s.ws + iq * 4 * 8 + kbase;

    #pragma unroll
    for (int ii = 0; ii < 4; ++ii) {
        // 6 x taps serve outputs mbase..mbase+3 (taps m..m+5 in padded coords)
        const float4 xlo = *reinterpret_cast<const float4*>(xrow + ii * XPITCH);
        const float2 xhi = *reinterpret_cast<const float2*>(xrow + ii * XPITCH + 4);
        const float xv[6] = { xlo.x, xlo.y, xlo.z, xlo.w, xhi.x, xhi.y };

        const float4 w0 = *reinterpret_cast<const float4*>(wrow + ii * 8);          // j=0
        const float4 w1 = *reinterpret_cast<const float4*>(wrow + ii * 8 + 512);    // j=1
        const float4 w2 = *reinterpret_cast<const float4*>(wrow + ii * 8 + 1024);   // j=2
        const float wj[3][4] = { {w0.x,w0.y,w0.z,w0.w},
                                 {w1.x,w1.y,w1.z,w1.w},
                                 {w2.x,w2.y,w2.z,w2.w} };

        #pragma unroll
        for (int kk = 0; kk < 4; ++kk)
            #pragma unroll
            for (int d = 0; d < 4; ++d)
                acc[kk][d] += xv[d] * wj[0][kk]
                            + xv[d + 1] * wj[1][kk]
                            + xv[d + 2] * wj[2][kk];
    }

    // all xs/ws reads done before red aliases the same smem
    __syncthreads();

    // --- write all 16 slabs in one stage: red[(iq*8 + kl)*56 + m] ---
    #pragma unroll
    for (int kk = 0; kk < 4; ++kk)
        *reinterpret_cast<float4*>(
            sm.red + (iq * 8 + kbase + kk) * 56 + mbase) =
            make_float4(acc[kk][0], acc[kk][1], acc[kk][2], acc[kk][3]);
    __syncthreads();

    // --- final: 448 threads = 8 k_local x 56 m; 16-way sum + rolled store ---
    {
        const int kl = tid / 56;
        const int m  = tid % 56;
        // two independent partial chains to halve dependent-add latency
        float s0 = 0.f, s1 = 0.f;
        #pragma unroll
        for (int q = 0; q < 8; ++q) {
            s0 += sm.red[((2 * q    ) * 8 + kl) * 56 + m];
            s1 += sm.red[((2 * q + 1) * 8 + kl) * 56 + m];
        }
        const int n_out = (n + 1) % 56;
        out[((o * 16 + kh * 8 + kl) * 56 + n_out) * 56 + m] = s0 + s1;
    }
}

extern "C" void kernel_launch(void* const* d_in, const int* in_sizes, int n_in,
                              void* d_out, int out_size)
{
    const float* x = (const float*)d_in[0];   // (1,128,56,56) fp32
    const float* W = (const float*)d_in[1];   // (64,16,3) fp32
    float* out     = (float*)d_out;           // (1,32,56,56) fp32

    dim3 grid(56, 2, 2);
    shiftconv_kernel<<<grid, NT>>>(x, W, out);
}